// round 14
// baseline (speedup 1.0000x reference)
#include <cuda_runtime.h>
#include <cuda_bf16.h>
#include <math.h>
#include <stdint.h>

#define FULL 0xffffffffu

// Problem constants
#define Bz 2
#define Sdim 2048
#define Edim 256
#define Hn 8
#define HD 32
#define WIN 129
#define OFF 64
#define MTOK (Bz*Sdim)          // 4096 token rows
#define KW 128                  // packed k-words per 256 floats
#define WPK (128*256)           // u32 words per packed weight matrix
#define NQROWS (Bz*Hn*Sdim)     // 32768 attention rows
#define PW 80                   // P words per row (160 local keys / 2)

// Scratch (no cudaMalloc allowed)
__device__ uint32_t g_xh[MTOK*KW];   // x+pe, bf16 hi, k-packed pairs
__device__ uint32_t g_xl[MTOK*KW];   // bf16 lo
__device__ uint32_t g_qh[MTOK*KW];   // q packed bf16 hi pairs (along E)
__device__ uint32_t g_ql[MTOK*KW];
__device__ uint32_t g_kh[MTOK*KW];   // k packed
__device__ uint32_t g_kl[MTOK*KW];
__device__ uint32_t g_vh[MTOK*KW];   // v packed (read as u16 elementwise)
__device__ uint32_t g_vl[MTOK*KW];
__device__ uint32_t g_ch[MTOK*KW];   // ctx bf16 hi packed
__device__ uint32_t g_cl[MTOK*KW];   // ctx bf16 lo packed
__device__ uint32_t g_wh[4*WPK];     // Wq,Wk,Wv,Wo packed [kp][n] bf16 hi
__device__ uint32_t g_wl[4*WPK];     // lo
__device__ uint32_t g_ph[NQROWS*PW]; // normalized P, bf16 hi packed
__device__ uint32_t g_pl[NQROWS*PW]; // bf16 lo packed

// ---------------------------------------------------------------------------
// helpers
// ---------------------------------------------------------------------------
__device__ __forceinline__ void split_bf16(float x, uint16_t& h, uint16_t& l) {
    __nv_bfloat16 bh = __float2bfloat16_rn(x);
    float r = x - __bfloat162float(bh);
    __nv_bfloat16 bl = __float2bfloat16_rn(r);
    h = __bfloat16_as_ushort(bh);
    l = __bfloat16_as_ushort(bl);
}
__device__ __forceinline__ uint32_t pack2(uint16_t e0, uint16_t e1) {
    return (uint32_t)e0 | ((uint32_t)e1 << 16);
}
__device__ __forceinline__ void split_pack2(float x0, float x1,
                                            uint32_t& wh, uint32_t& wl) {
    uint16_t h0, l0, h1, l1;
    split_bf16(x0, h0, l0);
    split_bf16(x1, h1, l1);
    wh = pack2(h0, h1);
    wl = pack2(l0, l1);
}
__device__ __forceinline__ void mma_bf16(float* acc, const uint32_t* a, const uint32_t* b) {
    asm volatile(
        "mma.sync.aligned.m16n8k16.row.col.f32.bf16.bf16.f32 "
        "{%0,%1,%2,%3}, {%4,%5,%6,%7}, {%8,%9}, {%0,%1,%2,%3};\n"
        : "+f"(acc[0]), "+f"(acc[1]), "+f"(acc[2]), "+f"(acc[3])
        : "r"(a[0]), "r"(a[1]), "r"(a[2]), "r"(a[3]), "r"(b[0]), "r"(b[1]));
}
__device__ __forceinline__ void cp16(void* smem, const void* g) {
    uint32_t s = (uint32_t)__cvta_generic_to_shared(smem);
    asm volatile("cp.async.cg.shared.global [%0], [%1], 16;\n" :: "r"(s), "l"(g));
}

// ---------------------------------------------------------------------------
// x + PE -> packed bf16 hi/lo pairs
// ---------------------------------------------------------------------------
__global__ void add_pe_pack_kernel(const float* __restrict__ x,
                                   uint32_t* __restrict__ yh,
                                   uint32_t* __restrict__ yl) {
    int i = blockIdx.x * 256 + threadIdx.x;   // MTOK*KW threads
    int e2 = i & (KW - 1);
    int m  = i >> 7;
    int s  = m & (Sdim - 1);
    float dv = expf((float)e2 * (-2.0f * 9.210340371976184f / 256.0f));
    float ang = (float)s * dv;
    float2 xv = *(const float2*)&x[m * Edim + 2 * e2];
    uint32_t wh, wl;
    split_pack2(xv.x + sinf(ang), xv.y + cosf(ang), wh, wl);
    yh[i] = wh;
    yl[i] = wl;
}

// ---------------------------------------------------------------------------
// Pack the 4 weight matrices: word [kp][n] = (W[2kp][n], W[2kp+1][n]) bf16
// ---------------------------------------------------------------------------
__global__ void pack_w_kernel(const float* __restrict__ Wq, const float* __restrict__ Wk,
                              const float* __restrict__ Wv, const float* __restrict__ Wo,
                              uint32_t* __restrict__ wh, uint32_t* __restrict__ wl) {
    int i = blockIdx.x * 256 + threadIdx.x;     // 4*WPK threads
    int wsel = i >> 15;
    int r    = i & (WPK - 1);
    int kp   = r >> 8;
    int n    = r & 255;
    const float* W = (wsel == 0) ? Wq : ((wsel == 1) ? Wk : ((wsel == 2) ? Wv : Wo));
    uint32_t hw, lw;
    split_pack2(W[(2 * kp) * Edim + n], W[(2 * kp + 1) * Edim + n], hw, lw);
    wh[i] = hw;
    wl[i] = lw;
}

// ---------------------------------------------------------------------------
// 3xBF16 tensor-core GEMM (unchanged from R13).
// Epilogue: fp32mode ? fp32+bias store : split-to-bf16-hi/lo packed store.
// ---------------------------------------------------------------------------
#define GBM 64
#define GBN 64
#define NSTAGE 4
#define PA 12
#define PB 72

__global__ __launch_bounds__(128) void gemm_tc_kernel(
    const uint32_t* __restrict__ Xh, const uint32_t* __restrict__ Xl,
    const uint32_t* __restrict__ Whb, const uint32_t* __restrict__ Wlb,
    const float* __restrict__ b0, const float* __restrict__ b1,
    const float* __restrict__ b2,
    uint32_t* __restrict__ Y0h, uint32_t* __restrict__ Y0l,
    uint32_t* __restrict__ Y1h, uint32_t* __restrict__ Y1l,
    uint32_t* __restrict__ Y2h, uint32_t* __restrict__ Y2l,
    float* __restrict__ Yf, int fp32mode)
{
    __shared__ uint32_t Ahs[NSTAGE][GBM][PA];
    __shared__ uint32_t Als[NSTAGE][GBM][PA];
    __shared__ uint32_t Bhs[NSTAGE][8][PB];
    __shared__ uint32_t Bls[NSTAGE][8][PB];

    const int t    = threadIdx.x;
    const int lane = t & 31;
    const int warp = t >> 5;
    const int warp_m = warp & 1;
    const int warp_n = warp >> 1;
    const int lr = lane >> 2;
    const int lc = lane & 3;

    const int bm = blockIdx.x * GBM;
    const int wsel = blockIdx.y >> 2;
    const int bn = (blockIdx.y & 3) * GBN;

    const uint32_t* Wh = Whb + wsel * WPK;
    const uint32_t* Wl = Wlb + wsel * WPK;
    const float* bias  = (wsel == 0) ? b0 : ((wsel == 1) ? b1 : b2);

    float acc[2][4][4];
#pragma unroll
    for (int mf = 0; mf < 2; ++mf)
#pragma unroll
        for (int nf = 0; nf < 4; ++nf)
#pragma unroll
            for (int r = 0; r < 4; ++r) acc[mf][nf][r] = 0.f;

    const int am  = t >> 1;
    const int aq  = (t & 1) * 4;
    const int br  = t >> 4;
    const int bq  = (t & 15) * 4;

#define LOAD_TILE(it, buf)                                                     \
    do {                                                                       \
        int kw0 = (it) * 8;                                                    \
        cp16(&Ahs[buf][am][aq], &Xh[(bm + am) * KW + kw0 + aq]);               \
        cp16(&Als[buf][am][aq], &Xl[(bm + am) * KW + kw0 + aq]);               \
        cp16(&Bhs[buf][br][bq], &Wh[(kw0 + br) * Edim + bn + bq]);             \
        cp16(&Bls[buf][br][bq], &Wl[(kw0 + br) * Edim + bn + bq]);             \
        asm volatile("cp.async.commit_group;\n");                              \
    } while (0)

    const int KITERS = 16;
    LOAD_TILE(0, 0);
    LOAD_TILE(1, 1);
    LOAD_TILE(2, 2);

    for (int it = 0; it < KITERS; ++it) {
        const int buf = it & (NSTAGE - 1);
        const int rem = KITERS - 1 - it;
        if (rem >= 2)      asm volatile("cp.async.wait_group 2;\n");
        else if (rem == 1) asm volatile("cp.async.wait_group 1;\n");
        else               asm volatile("cp.async.wait_group 0;\n");
        __syncthreads();

        if (it + 3 < KITERS) LOAD_TILE(it + 3, (it + 3) & (NSTAGE - 1));

        uint32_t ah[2][4], al[2][4], bh[4][2], bl[4][2];
#pragma unroll
        for (int mf = 0; mf < 2; ++mf) {
            int r = warp_m * 32 + mf * 16 + lr;
            ah[mf][0] = Ahs[buf][r][lc];
            ah[mf][1] = Ahs[buf][r + 8][lc];
            ah[mf][2] = Ahs[buf][r][lc + 4];
            ah[mf][3] = Ahs[buf][r + 8][lc + 4];
            al[mf][0] = Als[buf][r][lc];
            al[mf][1] = Als[buf][r + 8][lc];
            al[mf][2] = Als[buf][r][lc + 4];
            al[mf][3] = Als[buf][r + 8][lc + 4];
        }
#pragma unroll
        for (int nf = 0; nf < 4; ++nf) {
            int cn = warp_n * 32 + nf * 8 + lr;
            bh[nf][0] = Bhs[buf][lc][cn];
            bh[nf][1] = Bhs[buf][lc + 4][cn];
            bl[nf][0] = Bls[buf][lc][cn];
            bl[nf][1] = Bls[buf][lc + 4][cn];
        }
#pragma unroll
        for (int mf = 0; mf < 2; ++mf)
#pragma unroll
            for (int nf = 0; nf < 4; ++nf) {
                mma_bf16(acc[mf][nf], al[mf], bh[nf]);
                mma_bf16(acc[mf][nf], ah[mf], bl[nf]);
                mma_bf16(acc[mf][nf], ah[mf], bh[nf]);
            }
        __syncthreads();
    }

    // ---- epilogue ----
    if (fp32mode) {
        float* Y = Yf;
#pragma unroll
        for (int mf = 0; mf < 2; ++mf) {
            int r = bm + warp_m * 32 + mf * 16 + lr;
#pragma unroll
            for (int nf = 0; nf < 4; ++nf) {
                int cg = bn + warp_n * 32 + nf * 8 + 2 * lc;
                float bv0 = bias[cg], bv1 = bias[cg + 1];
                float2 v0 = make_float2(acc[mf][nf][0] + bv0, acc[mf][nf][1] + bv1);
                float2 v1 = make_float2(acc[mf][nf][2] + bv0, acc[mf][nf][3] + bv1);
                *(float2*)&Y[r * Edim + cg] = v0;
                *(float2*)&Y[(r + 8) * Edim + cg] = v1;
            }
        }
    } else {
        uint32_t* Yh = (wsel == 0) ? Y0h : ((wsel == 1) ? Y1h : Y2h);
        uint32_t* Yl = (wsel == 0) ? Y0l : ((wsel == 1) ? Y1l : Y2l);
#pragma unroll
        for (int mf = 0; mf < 2; ++mf) {
            int r = bm + warp_m * 32 + mf * 16 + lr;
#pragma unroll
            for (int nf = 0; nf < 4; ++nf) {
                int cg = bn + warp_n * 32 + nf * 8 + 2 * lc;
                int wj = cg >> 1;
                float bv0 = bias[cg], bv1 = bias[cg + 1];
                uint32_t hw, lw;
                split_pack2(acc[mf][nf][0] + bv0, acc[mf][nf][1] + bv1, hw, lw);
                Yh[r * KW + wj] = hw;
                Yl[r * KW + wj] = lw;
                split_pack2(acc[mf][nf][2] + bv0, acc[mf][nf][3] + bv1, hw, lw);
                Yh[(r + 8) * KW + wj] = hw;
                Yl[(r + 8) * KW + wj] = lw;
            }
        }
    }
#undef LOAD_TILE
}

// ---------------------------------------------------------------------------
// Attention kernel A: scores + softmax.
// Stages only K (transposed packed) + Q. ~27 KB static smem -> 8 CTAs/SM.
// Writes attn weights DIRECTLY from registers (exact fp32) and normalized P
// packed bf16 hi/lo to global for kernel B.
// ---------------------------------------------------------------------------
#define KSTR 168
#define QSTR 20
#define NROWS 160

__global__ __launch_bounds__(256) void attn_score_kernel(
    const uint32_t* __restrict__ qh, const uint32_t* __restrict__ ql,
    const uint32_t* __restrict__ kh, const uint32_t* __restrict__ kl,
    uint32_t* __restrict__ Pgh, uint32_t* __restrict__ Pgl,
    float* __restrict__ attn_out)
{
    __shared__ uint32_t khs[16 * KSTR];
    __shared__ uint32_t kls[16 * KSTR];
    __shared__ uint32_t qhs[32 * QSTR];
    __shared__ uint32_t qls[32 * QSTR];
    __shared__ float rmax[128];
    __shared__ float rsum[128];

    const int b    = blockIdx.z;
    const int h    = blockIdx.y;
    const int s0   = blockIdx.x * 32;
    const int t    = threadIdx.x;
    const int lane = t & 31;
    const int warp = t >> 5;
    const int warp_m = warp & 1;
    const int warp_n = warp >> 1;
    const int lr = lane >> 2;
    const int lc = lane & 3;

    const int wbase = (b * Sdim) * KW + h * 16;   // word base for q/k
    const int prow_base = (b * Hn + h) * Sdim;    // attention row base

    // ---- stage K: transpose copy words [tok][dw] -> [dw][key] ----
    for (int i = t; i < NROWS * 16; i += 256) {
        int r  = i >> 4;
        int dw = i & 15;
        int tok = min(max(s0 - OFF + r, 0), Sdim - 1);
        khs[dw * KSTR + r] = kh[wbase + tok * KW + dw];
        kls[dw * KSTR + r] = kl[wbase + tok * KW + dw];
    }
    // ---- stage Q: straight word copy ----
    for (int i = t; i < 32 * 16; i += 256) {
        int row = i >> 4;
        int dw  = i & 15;
        qhs[row * QSTR + dw] = qh[wbase + (s0 + row) * KW + dw];
        qls[row * QSTR + dw] = ql[wbase + (s0 + row) * KW + dw];
    }
    __syncthreads();

    // ---- scores: per warp S[16 q][40 keys] = 5 n-tiles x 2 k16-steps ----
    const int q0 = warp_m * 16 + lr;
    const int q1 = q0 + 8;

    float acc[5][4];
#pragma unroll
    for (int nt = 0; nt < 5; ++nt)
#pragma unroll
        for (int j = 0; j < 4; ++j) acc[nt][j] = 0.f;

#pragma unroll
    for (int s = 0; s < 2; ++s) {
        uint32_t ah[4], al[4];
        ah[0] = qhs[q0 * QSTR + s * 8 + lc];
        ah[1] = qhs[q1 * QSTR + s * 8 + lc];
        ah[2] = qhs[q0 * QSTR + s * 8 + lc + 4];
        ah[3] = qhs[q1 * QSTR + s * 8 + lc + 4];
        al[0] = qls[q0 * QSTR + s * 8 + lc];
        al[1] = qls[q1 * QSTR + s * 8 + lc];
        al[2] = qls[q0 * QSTR + s * 8 + lc + 4];
        al[3] = qls[q1 * QSTR + s * 8 + lc + 4];
#pragma unroll
        for (int nt = 0; nt < 5; ++nt) {
            int key = warp_n * 40 + nt * 8 + lr;
            uint32_t bh[2], bl[2];
            bh[0] = khs[(s * 8 + lc) * KSTR + key];
            bh[1] = khs[(s * 8 + lc + 4) * KSTR + key];
            bl[0] = kls[(s * 8 + lc) * KSTR + key];
            bl[1] = kls[(s * 8 + lc + 4) * KSTR + key];
            mma_bf16(acc[nt], al, bh);
            mma_bf16(acc[nt], ah, bl);
            mma_bf16(acc[nt], ah, bh);
        }
    }

    // ---- scale + band/sequence mask; row maxima ----
    const float scale = 0.17677669529663689f;  // 1/sqrt(32)
    float m0 = -INFINITY, m1 = -INFINITY;
#pragma unroll
    for (int nt = 0; nt < 5; ++nt) {
#pragma unroll
        for (int j = 0; j < 4; ++j) {
            int row = (j >= 2) ? q1 : q0;
            int key = warp_n * 40 + nt * 8 + 2 * lc + (j & 1);
            int w  = key - row;
            int kg = s0 - OFF + key;
            bool valid = (w >= 0) & (w <= 128) & (kg >= 0) & (kg < Sdim);
            float s = valid ? acc[nt][j] * scale : -1e9f;
            acc[nt][j] = s;
            if (j >= 2) m1 = fmaxf(m1, s); else m0 = fmaxf(m0, s);
        }
    }
    m0 = fmaxf(m0, __shfl_xor_sync(FULL, m0, 1));
    m0 = fmaxf(m0, __shfl_xor_sync(FULL, m0, 2));
    m1 = fmaxf(m1, __shfl_xor_sync(FULL, m1, 1));
    m1 = fmaxf(m1, __shfl_xor_sync(FULL, m1, 2));
    if (lc == 0) { rmax[q0 * 4 + warp_n] = m0; rmax[q1 * 4 + warp_n] = m1; }
    __syncthreads();

    float4 t0 = *(const float4*)&rmax[q0 * 4];
    float4 t1 = *(const float4*)&rmax[q1 * 4];
    float gm0 = fmaxf(fmaxf(t0.x, t0.y), fmaxf(t0.z, t0.w));
    float gm1 = fmaxf(fmaxf(t1.x, t1.y), fmaxf(t1.z, t1.w));

    float sum0 = 0.f, sum1 = 0.f;
#pragma unroll
    for (int nt = 0; nt < 5; ++nt) {
#pragma unroll
        for (int j = 0; j < 4; ++j) {
            float e = expf(acc[nt][j] - ((j >= 2) ? gm1 : gm0));
            acc[nt][j] = e;
            if (j >= 2) sum1 += e; else sum0 += e;
        }
    }
    sum0 += __shfl_xor_sync(FULL, sum0, 1);
    sum0 += __shfl_xor_sync(FULL, sum0, 2);
    sum1 += __shfl_xor_sync(FULL, sum1, 1);
    sum1 += __shfl_xor_sync(FULL, sum1, 2);
    if (lc == 0) { rsum[q0 * 4 + warp_n] = sum0; rsum[q1 * 4 + warp_n] = sum1; }
    __syncthreads();

    float4 u0 = *(const float4*)&rsum[q0 * 4];
    float4 u1 = *(const float4*)&rsum[q1 * 4];
    float inv0 = 1.f / (u0.x + u0.y + u0.z + u0.w);
    float inv1 = 1.f / (u1.x + u1.y + u1.z + u1.w);

    // ---- outputs, straight from registers ----
    const int prow0 = prow_base + s0 + q0;
    const int prow1 = prow_base + s0 + q1;
    const long arow0 = (long)prow0 * WIN;
    const long arow1 = (long)prow1 * WIN;

#pragma unroll
    for (int nt = 0; nt < 5; ++nt) {
        int keyA = warp_n * 40 + nt * 8 + 2 * lc;   // keys keyA, keyA+1
        float p0 = acc[nt][0] * inv0;
        float p1 = acc[nt][1] * inv0;
        float p2 = acc[nt][2] * inv1;
        float p3 = acc[nt][3] * inv1;

        if (attn_out) {
            unsigned w;
            w = (unsigned)(keyA - q0);     if (w <= 128u) attn_out[arow0 + w] = p0;
            w = (unsigned)(keyA + 1 - q0); if (w <= 128u) attn_out[arow0 + w] = p1;
            w = (unsigned)(keyA - q1);     if (w <= 128u) attn_out[arow1 + w] = p2;
            w = (unsigned)(keyA + 1 - q1); if (w <= 128u) attn_out[arow1 + w] = p3;
        }

        int wd = warp_n * 20 + nt * 4 + lc;  // = keyA >> 1
        uint32_t hw, lw;
        split_pack2(p0, p1, hw, lw);
        Pgh[(long)prow0 * PW + wd] = hw;
        Pgl[(long)prow0 * PW + wd] = lw;
        split_pack2(p2, p3, hw, lw);
        Pgh[(long)prow1 * PW + wd] = hw;
        Pgl[(long)prow1 * PW + wd] = lw;
    }
}

// ---------------------------------------------------------------------------
// Attention kernel B: ctx = P(32x160) @ V(160x32), bf16-3x.
// Stages only V (~26 KB static smem -> 8 CTAs/SM); P A-fragments loaded
// straight from global (L2-resident). One __syncthreads total.
// ---------------------------------------------------------------------------
#define VSTR 40

__global__ __launch_bounds__(256) void attn_ctx_kernel(
    const uint32_t* __restrict__ Pgh, const uint32_t* __restrict__ Pgl,
    const uint32_t* __restrict__ vh, const uint32_t* __restrict__ vl,
    uint32_t* __restrict__ ctx_h, uint32_t* __restrict__ ctx_l)
{
    __shared__ uint32_t vhs[80 * VSTR];
    __shared__ uint32_t vls[80 * VSTR];

    const int b    = blockIdx.z;
    const int h    = blockIdx.y;
    const int s0   = blockIdx.x * 32;
    const int t    = threadIdx.x;
    const int lane = t & 31;
    const int warp = t >> 5;
    const int warp_m = warp & 1;
    const int warp_n = warp >> 1;
    const int lr = lane >> 2;
    const int lc = lane & 3;

    const uint16_t* vh16 = (const uint16_t*)vh;
    const uint16_t* vl16 = (const uint16_t*)vl;
    const int ebase = (b * Sdim) * Edim + h * HD;
    const int prow_base = (b * Hn + h) * Sdim;

    // ---- stage V: pack token-pairs from elementwise bf16 ----
    for (int i = t; i < 80 * 32; i += 256) {
        int kw  = i >> 5;
        int dim = i & 31;
        int tok0 = min(max(s0 - OFF + 2 * kw, 0), Sdim - 1);
        int tok1 = min(max(s0 - OFF + 2 * kw + 1, 0), Sdim - 1);
        vhs[kw * VSTR + dim] = pack2(vh16[ebase + tok0 * Edim + dim],
                                     vh16[ebase + tok1 * Edim + dim]);
        vls[kw * VSTR + dim] = pack2(vl16[ebase + tok0 * Edim + dim],
                                     vl16[ebase + tok1 * Edim + dim]);
    }
    __syncthreads();

    const int q0 = warp_m * 16 + lr;
    const int q1 = q0 + 8;
    const uint32_t* p0h = Pgh + (long)(prow_base + s0 + q0) * PW;
    const uint32_t* p1h = Pgh + (long)(prow_base + s0 + q1) * PW;
    const uint32_t* p0l = Pgl + (long)(prow_base + s0 + q0) * PW;
    const uint32_t* p1l = Pgl + (long)(prow_base + s0 + q1) * PW;

    float c[4] = {0.f, 0.f, 0.f, 0.f};
#pragma unroll
    for (int s = 0; s < 10; ++s) {
        uint32_t ah[4], al[4], bh[2], bl[2];
        ah[0] = p0h[s * 8 + lc];
        ah[1] = p1h[s * 8 + lc];
        ah[2] = p0h[s * 8 + lc + 4];
        ah[3] = p1h[s * 8 + lc + 4];
        al[0] = p0l[s * 8 + lc];
        al[1] = p1l[s * 8 + lc];
        al[2] = p0l[s * 8 + lc + 4];
        al[3] = p1l[s * 8 + lc + 4];
        bh[0] = vhs[(s * 8 + lc) * VSTR + warp_n * 8 + lr];
        bh[1] = vhs[(s * 8 + lc + 4) * VSTR + warp_n * 8 + lr];
        bl[0] = vls[(s * 8 + lc) * VSTR + warp_n * 8 + lr];
        bl[1] = vls[(s * 8 + lc + 4) * VSTR + warp_n * 8 + lr];
        mma_bf16(c, al, bh);
        mma_bf16(c, ah, bl);
        mma_bf16(c, ah, bh);
    }

    // ---- pack ctx to bf16 hi/lo words for the O projection ----
    {
        int pkbase = (b * Sdim) * KW + h * (HD / 2);
        int wd = warp_n * 4 + lc;
        uint32_t hw, lw;
        split_pack2(c[0], c[1], hw, lw);
        ctx_h[pkbase + (s0 + q0) * KW + wd] = hw;
        ctx_l[pkbase + (s0 + q0) * KW + wd] = lw;
        split_pack2(c[2], c[3], hw, lw);
        ctx_h[pkbase + (s0 + q1) * KW + wd] = hw;
        ctx_l[pkbase + (s0 + q1) * KW + wd] = lw;
    }
}

// ---------------------------------------------------------------------------
extern "C" void kernel_launch(void* const* d_in, const int* in_sizes, int n_in,
                              void* d_out, int out_size) {
    const float* x  = (const float*)d_in[0];
    const float* Wq = (const float*)d_in[1];
    const float* bq = (const float*)d_in[2];
    const float* Wk = (const float*)d_in[3];
    const float* bk = (const float*)d_in[4];
    const float* Wv = (const float*)d_in[5];
    const float* bv = (const float*)d_in[6];
    const float* Wo = (const float*)d_in[7];
    const float* bo = (const float*)d_in[8];
    float* out = (float*)d_out;

    uint32_t *xh, *xl, *qh, *ql, *kh, *kl, *vh, *vl, *ch, *cl, *wh, *wl, *ph, *pl;
    cudaGetSymbolAddress((void**)&xh, g_xh);
    cudaGetSymbolAddress((void**)&xl, g_xl);
    cudaGetSymbolAddress((void**)&qh, g_qh);
    cudaGetSymbolAddress((void**)&ql, g_ql);
    cudaGetSymbolAddress((void**)&kh, g_kh);
    cudaGetSymbolAddress((void**)&kl, g_kl);
    cudaGetSymbolAddress((void**)&vh, g_vh);
    cudaGetSymbolAddress((void**)&vl, g_vl);
    cudaGetSymbolAddress((void**)&ch, g_ch);
    cudaGetSymbolAddress((void**)&cl, g_cl);
    cudaGetSymbolAddress((void**)&wh, g_wh);
    cudaGetSymbolAddress((void**)&wl, g_wl);
    cudaGetSymbolAddress((void**)&ph, g_ph);
    cudaGetSymbolAddress((void**)&pl, g_pl);

    const long OUT_ELEMS  = (long)Bz * Sdim * Edim;                 // 1,048,576
    const long ATTN_ELEMS = (long)Bz * Hn * Sdim * WIN;             // 4,227,072
    float* attn_out = nullptr;
    if ((long)out_size >= OUT_ELEMS + ATTN_ELEMS) attn_out = out + OUT_ELEMS;

    add_pe_pack_kernel<<<MTOK * KW / 256, 256>>>(x, xh, xl);
    pack_w_kernel<<<4 * WPK / 256, 256>>>(Wq, Wk, Wv, Wo, wh, wl);

    // Fused Q/K/V projections -> pre-split bf16 hi/lo outputs
    gemm_tc_kernel<<<dim3(MTOK / GBM, 12), 128>>>(
        xh, xl, wh, wl, bq, bk, bv,
        qh, ql, kh, kl, vh, vl, nullptr, 0);

    dim3 ag(Sdim / 32, Hn, Bz);
    attn_score_kernel<<<ag, 256>>>(qh, ql, kh, kl, ph, pl, attn_out);
    attn_ctx_kernel<<<ag, 256>>>(ph, pl, vh, vl, ch, cl);

    // Output projection: fp32 out (weights index 3)
    gemm_tc_kernel<<<dim3(MTOK / GBM, 4), 128>>>(
        ch, cl, wh + 3 * WPK, wl + 3 * WPK, bo, bo, bo,
        nullptr, nullptr, nullptr, nullptr, nullptr, nullptr, out, 1);
}

// round 15
// speedup vs baseline: 1.2410x; 1.2410x over previous
#include <cuda_runtime.h>
#include <cuda_bf16.h>
#include <math.h>
#include <stdint.h>

#define FULL 0xffffffffu

// Problem constants
#define Bz 2
#define Sdim 2048
#define Edim 256
#define Hn 8
#define HD 32
#define WIN 129
#define OFF 64
#define MTOK (Bz*Sdim)          // 4096 token rows
#define KW 128                  // packed k-words per 256 floats
#define WPK (128*256)           // u32 words per packed weight matrix

// Scratch (no cudaMalloc allowed)
__device__ uint32_t g_xh[MTOK*KW];   // x+pe, bf16 hi, k-packed pairs
__device__ uint32_t g_xl[MTOK*KW];   // bf16 lo
__device__ uint32_t g_qh[MTOK*KW];   // q packed bf16 hi pairs (along E)
__device__ uint32_t g_ql[MTOK*KW];
__device__ uint32_t g_kh[MTOK*KW];   // k packed
__device__ uint32_t g_kl[MTOK*KW];
__device__ uint32_t g_vh[MTOK*KW];   // v packed (read as u16 elementwise)
__device__ uint32_t g_vl[MTOK*KW];
__device__ uint32_t g_ch[MTOK*KW];   // ctx bf16 hi packed
__device__ uint32_t g_cl[MTOK*KW];   // ctx bf16 lo packed
__device__ uint32_t g_wh[4*WPK];     // Wq,Wk,Wv,Wo packed [kp][n] bf16 hi
__device__ uint32_t g_wl[4*WPK];     // lo

// ---------------------------------------------------------------------------
// helpers
// ---------------------------------------------------------------------------
__device__ __forceinline__ void split_bf16(float x, uint16_t& h, uint16_t& l) {
    __nv_bfloat16 bh = __float2bfloat16_rn(x);
    float r = x - __bfloat162float(bh);
    __nv_bfloat16 bl = __float2bfloat16_rn(r);
    h = __bfloat16_as_ushort(bh);
    l = __bfloat16_as_ushort(bl);
}
__device__ __forceinline__ uint32_t pack2(uint16_t e0, uint16_t e1) {
    return (uint32_t)e0 | ((uint32_t)e1 << 16);
}
__device__ __forceinline__ void split_pack2(float x0, float x1,
                                            uint32_t& wh, uint32_t& wl) {
    uint16_t h0, l0, h1, l1;
    split_bf16(x0, h0, l0);
    split_bf16(x1, h1, l1);
    wh = pack2(h0, h1);
    wl = pack2(l0, l1);
}
__device__ __forceinline__ void mma_bf16(float* acc, const uint32_t* a, const uint32_t* b) {
    asm volatile(
        "mma.sync.aligned.m16n8k16.row.col.f32.bf16.bf16.f32 "
        "{%0,%1,%2,%3}, {%4,%5,%6,%7}, {%8,%9}, {%0,%1,%2,%3};\n"
        : "+f"(acc[0]), "+f"(acc[1]), "+f"(acc[2]), "+f"(acc[3])
        : "r"(a[0]), "r"(a[1]), "r"(a[2]), "r"(a[3]), "r"(b[0]), "r"(b[1]));
}
__device__ __forceinline__ void cp16(void* smem, const void* g) {
    uint32_t s = (uint32_t)__cvta_generic_to_shared(smem);
    asm volatile("cp.async.cg.shared.global [%0], [%1], 16;\n" :: "r"(s), "l"(g));
}

// ---------------------------------------------------------------------------
// x + PE -> packed bf16 hi/lo pairs
// ---------------------------------------------------------------------------
__global__ void add_pe_pack_kernel(const float* __restrict__ x,
                                   uint32_t* __restrict__ yh,
                                   uint32_t* __restrict__ yl) {
    int i = blockIdx.x * 256 + threadIdx.x;   // MTOK*KW threads
    int e2 = i & (KW - 1);
    int m  = i >> 7;
    int s  = m & (Sdim - 1);
    float dv = expf((float)e2 * (-2.0f * 9.210340371976184f / 256.0f));
    float ang = (float)s * dv;
    float2 xv = *(const float2*)&x[m * Edim + 2 * e2];
    uint32_t wh, wl;
    split_pack2(xv.x + sinf(ang), xv.y + cosf(ang), wh, wl);
    yh[i] = wh;
    yl[i] = wl;
}

// ---------------------------------------------------------------------------
// Pack the 4 weight matrices: word [kp][n] = (W[2kp][n], W[2kp+1][n]) bf16
// ---------------------------------------------------------------------------
__global__ void pack_w_kernel(const float* __restrict__ Wq, const float* __restrict__ Wk,
                              const float* __restrict__ Wv, const float* __restrict__ Wo,
                              uint32_t* __restrict__ wh, uint32_t* __restrict__ wl) {
    int i = blockIdx.x * 256 + threadIdx.x;     // 4*WPK threads
    int wsel = i >> 15;
    int r    = i & (WPK - 1);
    int kp   = r >> 8;
    int n    = r & 255;
    const float* W = (wsel == 0) ? Wq : ((wsel == 1) ? Wk : ((wsel == 2) ? Wv : Wo));
    uint32_t hw, lw;
    split_pack2(W[(2 * kp) * Edim + n], W[(2 * kp + 1) * Edim + n], hw, lw);
    wh[i] = hw;
    wl[i] = lw;
}

// ---------------------------------------------------------------------------
// 3xBF16 tensor-core GEMM (unchanged from R13).
// Epilogue: fp32mode ? fp32+bias store : split-to-bf16-hi/lo packed store.
// ---------------------------------------------------------------------------
#define GBM 64
#define GBN 64
#define NSTAGE 4
#define PA 12
#define PB 72

__global__ __launch_bounds__(128) void gemm_tc_kernel(
    const uint32_t* __restrict__ Xh, const uint32_t* __restrict__ Xl,
    const uint32_t* __restrict__ Whb, const uint32_t* __restrict__ Wlb,
    const float* __restrict__ b0, const float* __restrict__ b1,
    const float* __restrict__ b2,
    uint32_t* __restrict__ Y0h, uint32_t* __restrict__ Y0l,
    uint32_t* __restrict__ Y1h, uint32_t* __restrict__ Y1l,
    uint32_t* __restrict__ Y2h, uint32_t* __restrict__ Y2l,
    float* __restrict__ Yf, int fp32mode)
{
    __shared__ uint32_t Ahs[NSTAGE][GBM][PA];
    __shared__ uint32_t Als[NSTAGE][GBM][PA];
    __shared__ uint32_t Bhs[NSTAGE][8][PB];
    __shared__ uint32_t Bls[NSTAGE][8][PB];

    const int t    = threadIdx.x;
    const int lane = t & 31;
    const int warp = t >> 5;
    const int warp_m = warp & 1;
    const int warp_n = warp >> 1;
    const int lr = lane >> 2;
    const int lc = lane & 3;

    const int bm = blockIdx.x * GBM;
    const int wsel = blockIdx.y >> 2;
    const int bn = (blockIdx.y & 3) * GBN;

    const uint32_t* Wh = Whb + wsel * WPK;
    const uint32_t* Wl = Wlb + wsel * WPK;
    const float* bias  = (wsel == 0) ? b0 : ((wsel == 1) ? b1 : b2);

    float acc[2][4][4];
#pragma unroll
    for (int mf = 0; mf < 2; ++mf)
#pragma unroll
        for (int nf = 0; nf < 4; ++nf)
#pragma unroll
            for (int r = 0; r < 4; ++r) acc[mf][nf][r] = 0.f;

    const int am  = t >> 1;
    const int aq  = (t & 1) * 4;
    const int br  = t >> 4;
    const int bq  = (t & 15) * 4;

#define LOAD_TILE(it, buf)                                                     \
    do {                                                                       \
        int kw0 = (it) * 8;                                                    \
        cp16(&Ahs[buf][am][aq], &Xh[(bm + am) * KW + kw0 + aq]);               \
        cp16(&Als[buf][am][aq], &Xl[(bm + am) * KW + kw0 + aq]);               \
        cp16(&Bhs[buf][br][bq], &Wh[(kw0 + br) * Edim + bn + bq]);             \
        cp16(&Bls[buf][br][bq], &Wl[(kw0 + br) * Edim + bn + bq]);             \
        asm volatile("cp.async.commit_group;\n");                              \
    } while (0)

    const int KITERS = 16;
    LOAD_TILE(0, 0);
    LOAD_TILE(1, 1);
    LOAD_TILE(2, 2);

    for (int it = 0; it < KITERS; ++it) {
        const int buf = it & (NSTAGE - 1);
        const int rem = KITERS - 1 - it;
        if (rem >= 2)      asm volatile("cp.async.wait_group 2;\n");
        else if (rem == 1) asm volatile("cp.async.wait_group 1;\n");
        else               asm volatile("cp.async.wait_group 0;\n");
        __syncthreads();

        if (it + 3 < KITERS) LOAD_TILE(it + 3, (it + 3) & (NSTAGE - 1));

        uint32_t ah[2][4], al[2][4], bh[4][2], bl[4][2];
#pragma unroll
        for (int mf = 0; mf < 2; ++mf) {
            int r = warp_m * 32 + mf * 16 + lr;
            ah[mf][0] = Ahs[buf][r][lc];
            ah[mf][1] = Ahs[buf][r + 8][lc];
            ah[mf][2] = Ahs[buf][r][lc + 4];
            ah[mf][3] = Ahs[buf][r + 8][lc + 4];
            al[mf][0] = Als[buf][r][lc];
            al[mf][1] = Als[buf][r + 8][lc];
            al[mf][2] = Als[buf][r][lc + 4];
            al[mf][3] = Als[buf][r + 8][lc + 4];
        }
#pragma unroll
        for (int nf = 0; nf < 4; ++nf) {
            int cn = warp_n * 32 + nf * 8 + lr;
            bh[nf][0] = Bhs[buf][lc][cn];
            bh[nf][1] = Bhs[buf][lc + 4][cn];
            bl[nf][0] = Bls[buf][lc][cn];
            bl[nf][1] = Bls[buf][lc + 4][cn];
        }
#pragma unroll
        for (int mf = 0; mf < 2; ++mf)
#pragma unroll
            for (int nf = 0; nf < 4; ++nf) {
                mma_bf16(acc[mf][nf], al[mf], bh[nf]);
                mma_bf16(acc[mf][nf], ah[mf], bl[nf]);
                mma_bf16(acc[mf][nf], ah[mf], bh[nf]);
            }
        __syncthreads();
    }

    // ---- epilogue ----
    if (fp32mode) {
        float* Y = Yf;
#pragma unroll
        for (int mf = 0; mf < 2; ++mf) {
            int r = bm + warp_m * 32 + mf * 16 + lr;
#pragma unroll
            for (int nf = 0; nf < 4; ++nf) {
                int cg = bn + warp_n * 32 + nf * 8 + 2 * lc;
                float bv0 = bias[cg], bv1 = bias[cg + 1];
                float2 v0 = make_float2(acc[mf][nf][0] + bv0, acc[mf][nf][1] + bv1);
                float2 v1 = make_float2(acc[mf][nf][2] + bv0, acc[mf][nf][3] + bv1);
                *(float2*)&Y[r * Edim + cg] = v0;
                *(float2*)&Y[(r + 8) * Edim + cg] = v1;
            }
        }
    } else {
        uint32_t* Yh = (wsel == 0) ? Y0h : ((wsel == 1) ? Y1h : Y2h);
        uint32_t* Yl = (wsel == 0) ? Y0l : ((wsel == 1) ? Y1l : Y2l);
#pragma unroll
        for (int mf = 0; mf < 2; ++mf) {
            int r = bm + warp_m * 32 + mf * 16 + lr;
#pragma unroll
            for (int nf = 0; nf < 4; ++nf) {
                int cg = bn + warp_n * 32 + nf * 8 + 2 * lc;
                int wj = cg >> 1;
                float bv0 = bias[cg], bv1 = bias[cg + 1];
                uint32_t hw, lw;
                split_pack2(acc[mf][nf][0] + bv0, acc[mf][nf][1] + bv1, hw, lw);
                Yh[r * KW + wj] = hw;
                Yl[r * KW + wj] = lw;
                split_pack2(acc[mf][nf][2] + bv0, acc[mf][nf][3] + bv1, hw, lw);
                Yh[(r + 8) * KW + wj] = hw;
                Yl[(r + 8) * KW + wj] = lw;
            }
        }
    }
#undef LOAD_TILE
}

// ---------------------------------------------------------------------------
// Fused attention: each warp owns COMPLETE score rows (16 q x 144 keys), so
// softmax is shfl-only and P converts C-frag -> A-frag in registers (no smem
// round trip). Block = 128 thr / 4 warps = 64 queries. ONE __syncthreads.
// Smem: K [dword][key] stride 200, V [kword][dim] stride 40, Q [row][dword]
// stride 20; all bf16 hi/lo packed, all fragment loads conflict-free.
// ---------------------------------------------------------------------------
#define QT 64
#define WROWS 192
#define KST 200
#define VST 40
#define QST 20

#define AKH 0
#define AKL (AKH + 16*KST)        // 3200
#define AVH (AKL + 16*KST)        // 6400
#define AVL (AVH + 96*VST)        // 10240
#define AQH (AVL + 96*VST)        // 14080
#define AQL (AQH + QT*QST)        // 15360
#define ASMW (AQL + QT*QST)       // 16640 words = 66560 B

__global__ __launch_bounds__(128) void attn_fused_kernel(
    const uint32_t* __restrict__ qh, const uint32_t* __restrict__ ql,
    const uint32_t* __restrict__ kh, const uint32_t* __restrict__ kl,
    const uint32_t* __restrict__ vh, const uint32_t* __restrict__ vl,
    uint32_t* __restrict__ ctx_h, uint32_t* __restrict__ ctx_l,
    float* __restrict__ attn_out)
{
    extern __shared__ uint32_t smu[];
    uint32_t* khs = smu + AKH;
    uint32_t* kls = smu + AKL;
    uint32_t* vhs = smu + AVH;
    uint32_t* vls = smu + AVL;
    uint32_t* qhs = smu + AQH;
    uint32_t* qls = smu + AQL;

    const int b    = blockIdx.z;
    const int h    = blockIdx.y;
    const int s0   = blockIdx.x * QT;
    const int gw0  = s0 - OFF;            // global key of local row 0
    const int t    = threadIdx.x;
    const int lane = t & 31;
    const int warp = t >> 5;              // 0..3, rows 16*warp..+15
    const int lr = lane >> 2;
    const int lc = lane & 3;

    const int wbase = (b * Sdim) * KW + h * 16;
    const uint16_t* vh16 = (const uint16_t*)vh;
    const uint16_t* vl16 = (const uint16_t*)vl;
    const int ebase = (b * Sdim) * Edim + h * HD;

    // ---- stage K: [tok][dw] -> [dw][key] ----
    for (int i = t; i < WROWS * 16; i += 128) {
        int r  = i >> 4;
        int dw = i & 15;
        int tok = min(max(gw0 + r, 0), Sdim - 1);
        khs[dw * KST + r] = kh[wbase + tok * KW + dw];
        kls[dw * KST + r] = kl[wbase + tok * KW + dw];
    }
    // ---- stage V: pack token-pairs ----
    for (int i = t; i < 96 * 32; i += 128) {
        int kw  = i >> 5;
        int dim = i & 31;
        int tok0 = min(max(gw0 + 2 * kw, 0), Sdim - 1);
        int tok1 = min(max(gw0 + 2 * kw + 1, 0), Sdim - 1);
        vhs[kw * VST + dim] = pack2(vh16[ebase + tok0 * Edim + dim],
                                    vh16[ebase + tok1 * Edim + dim]);
        vls[kw * VST + dim] = pack2(vl16[ebase + tok0 * Edim + dim],
                                    vl16[ebase + tok1 * Edim + dim]);
    }
    // ---- stage Q ----
    for (int i = t; i < QT * 16; i += 128) {
        int row = i >> 4;
        int dw  = i & 15;
        qhs[row * QST + dw] = qh[wbase + (s0 + row) * KW + dw];
        qls[row * QST + dw] = ql[wbase + (s0 + row) * KW + dw];
    }
    __syncthreads();

    // ---- scores: S[16 q][144 keys] = 18 n-tiles x 2 k16-steps, bf16-3x ----
    const int qr = 16 * warp + lr;        // local row (q0 part)
    float acc[18][4];
#pragma unroll
    for (int nt = 0; nt < 18; ++nt)
#pragma unroll
        for (int j = 0; j < 4; ++j) acc[nt][j] = 0.f;

#pragma unroll
    for (int s = 0; s < 2; ++s) {
        uint32_t ah[4], al[4];
        ah[0] = qhs[qr * QST + s * 8 + lc];
        ah[1] = qhs[(qr + 8) * QST + s * 8 + lc];
        ah[2] = qhs[qr * QST + s * 8 + lc + 4];
        ah[3] = qhs[(qr + 8) * QST + s * 8 + lc + 4];
        al[0] = qls[qr * QST + s * 8 + lc];
        al[1] = qls[(qr + 8) * QST + s * 8 + lc];
        al[2] = qls[qr * QST + s * 8 + lc + 4];
        al[3] = qls[(qr + 8) * QST + s * 8 + lc + 4];
#pragma unroll
        for (int nt = 0; nt < 18; ++nt) {
            int keyL = 16 * warp + nt * 8 + lr;
            uint32_t bh[2], bl[2];
            bh[0] = khs[(s * 8 + lc) * KST + keyL];
            bh[1] = khs[(s * 8 + lc + 4) * KST + keyL];
            bl[0] = kls[(s * 8 + lc) * KST + keyL];
            bl[1] = kls[(s * 8 + lc + 4) * KST + keyL];
            mma_bf16(acc[nt], al, bh);
            mma_bf16(acc[nt], ah, bl);
            mma_bf16(acc[nt], ah, bh);
        }
    }

    // ---- scale + band mask + in-warp softmax (rows fully warp-local) ----
    const float scale = 0.17677669529663689f;  // 1/sqrt(32)
    const int q0g = s0 + 16 * warp + lr;
    const int q1g = q0g + 8;
    float m0 = -INFINITY, m1 = -INFINITY;
#pragma unroll
    for (int nt = 0; nt < 18; ++nt) {
#pragma unroll
        for (int j = 0; j < 4; ++j) {
            int row = (j >= 2) ? q1g : q0g;
            int kg  = gw0 + 16 * warp + nt * 8 + 2 * lc + (j & 1);
            bool valid = ((unsigned)(kg - row + OFF) <= 128u) &
                         (kg >= 0) & (kg < Sdim);
            float sv = valid ? acc[nt][j] * scale : -1e9f;
            acc[nt][j] = sv;
            if (j >= 2) m1 = fmaxf(m1, sv); else m0 = fmaxf(m0, sv);
        }
    }
    m0 = fmaxf(m0, __shfl_xor_sync(FULL, m0, 1));
    m0 = fmaxf(m0, __shfl_xor_sync(FULL, m0, 2));
    m1 = fmaxf(m1, __shfl_xor_sync(FULL, m1, 1));
    m1 = fmaxf(m1, __shfl_xor_sync(FULL, m1, 2));

    float sum0 = 0.f, sum1 = 0.f;
#pragma unroll
    for (int nt = 0; nt < 18; ++nt) {
#pragma unroll
        for (int j = 0; j < 4; ++j) {
            float e = expf(acc[nt][j] - ((j >= 2) ? m1 : m0));
            acc[nt][j] = e;
            if (j >= 2) sum1 += e; else sum0 += e;
        }
    }
    sum0 += __shfl_xor_sync(FULL, sum0, 1);
    sum0 += __shfl_xor_sync(FULL, sum0, 2);
    sum1 += __shfl_xor_sync(FULL, sum1, 1);
    sum1 += __shfl_xor_sync(FULL, sum1, 2);
    float inv0 = 1.f / sum0;
    float inv1 = 1.f / sum1;

    // ---- ctx = P @ V with in-register C-frag -> A-frag conversion ----
    const long arow0 = (long)((b * Hn + h) * Sdim + q0g) * WIN;
    const long arow1 = (long)((b * Hn + h) * Sdim + q1g) * WIN;

    float c[4][4];
#pragma unroll
    for (int nf = 0; nf < 4; ++nf)
#pragma unroll
        for (int j = 0; j < 4; ++j) c[nf][j] = 0.f;

#pragma unroll
    for (int s = 0; s < 9; ++s) {
        // normalized P for score tiles 2s (k-lo) and 2s+1 (k-hi)
        float p00 = acc[2*s][0] * inv0,   p01 = acc[2*s][1] * inv0;
        float p02 = acc[2*s][2] * inv1,   p03 = acc[2*s][3] * inv1;
        float p10 = acc[2*s+1][0] * inv0, p11 = acc[2*s+1][1] * inv0;
        float p12 = acc[2*s+1][2] * inv1, p13 = acc[2*s+1][3] * inv1;

        if (attn_out) {
            int kgA = gw0 + 16 * warp + 16 * s + 2 * lc;   // tile 2s keys
            unsigned w;
            w = (unsigned)(kgA - q0g + OFF);     if (w <= 128u) attn_out[arow0 + w] = p00;
            w = (unsigned)(kgA + 1 - q0g + OFF); if (w <= 128u) attn_out[arow0 + w] = p01;
            w = (unsigned)(kgA - q1g + OFF);     if (w <= 128u) attn_out[arow1 + w] = p02;
            w = (unsigned)(kgA + 1 - q1g + OFF); if (w <= 128u) attn_out[arow1 + w] = p03;
            int kgB = kgA + 8;                             // tile 2s+1 keys
            w = (unsigned)(kgB - q0g + OFF);     if (w <= 128u) attn_out[arow0 + w] = p10;
            w = (unsigned)(kgB + 1 - q0g + OFF); if (w <= 128u) attn_out[arow0 + w] = p11;
            w = (unsigned)(kgB - q1g + OFF);     if (w <= 128u) attn_out[arow1 + w] = p12;
            w = (unsigned)(kgB + 1 - q1g + OFF); if (w <= 128u) attn_out[arow1 + w] = p13;
        }

        uint32_t Ah[4], Al[4];
        split_pack2(p00, p01, Ah[0], Al[0]);   // row q0, k-lo
        split_pack2(p02, p03, Ah[1], Al[1]);   // row q1, k-lo
        split_pack2(p10, p11, Ah[2], Al[2]);   // row q0, k-hi
        split_pack2(p12, p13, Ah[3], Al[3]);   // row q1, k-hi

        int kwb = 8 * warp + 8 * s;
#pragma unroll
        for (int nf = 0; nf < 4; ++nf) {
            int dim = nf * 8 + lr;
            uint32_t Bh[2], Bl[2];
            Bh[0] = vhs[(kwb + lc) * VST + dim];
            Bh[1] = vhs[(kwb + lc + 4) * VST + dim];
            Bl[0] = vls[(kwb + lc) * VST + dim];
            Bl[1] = vls[(kwb + lc + 4) * VST + dim];
            mma_bf16(c[nf], Al, Bh);
            mma_bf16(c[nf], Ah, Bl);
            mma_bf16(c[nf], Ah, Bh);
        }
    }

    // ---- pack ctx to bf16 hi/lo words for the O projection ----
    {
        int pkbase = (b * Sdim) * KW + h * (HD / 2);
#pragma unroll
        for (int nf = 0; nf < 4; ++nf) {
            int wd = nf * 4 + lc;
            uint32_t hw, lw;
            split_pack2(c[nf][0], c[nf][1], hw, lw);
            ctx_h[pkbase + q0g * KW + wd] = hw;
            ctx_l[pkbase + q0g * KW + wd] = lw;
            split_pack2(c[nf][2], c[nf][3], hw, lw);
            ctx_h[pkbase + q1g * KW + wd] = hw;
            ctx_l[pkbase + q1g * KW + wd] = lw;
        }
    }
}

// ---------------------------------------------------------------------------
extern "C" void kernel_launch(void* const* d_in, const int* in_sizes, int n_in,
                              void* d_out, int out_size) {
    const float* x  = (const float*)d_in[0];
    const float* Wq = (const float*)d_in[1];
    const float* bq = (const float*)d_in[2];
    const float* Wk = (const float*)d_in[3];
    const float* bk = (const float*)d_in[4];
    const float* Wv = (const float*)d_in[5];
    const float* bv = (const float*)d_in[6];
    const float* Wo = (const float*)d_in[7];
    const float* bo = (const float*)d_in[8];
    float* out = (float*)d_out;

    uint32_t *xh, *xl, *qh, *ql, *kh, *kl, *vh, *vl, *ch, *cl, *wh, *wl;
    cudaGetSymbolAddress((void**)&xh, g_xh);
    cudaGetSymbolAddress((void**)&xl, g_xl);
    cudaGetSymbolAddress((void**)&qh, g_qh);
    cudaGetSymbolAddress((void**)&ql, g_ql);
    cudaGetSymbolAddress((void**)&kh, g_kh);
    cudaGetSymbolAddress((void**)&kl, g_kl);
    cudaGetSymbolAddress((void**)&vh, g_vh);
    cudaGetSymbolAddress((void**)&vl, g_vl);
    cudaGetSymbolAddress((void**)&ch, g_ch);
    cudaGetSymbolAddress((void**)&cl, g_cl);
    cudaGetSymbolAddress((void**)&wh, g_wh);
    cudaGetSymbolAddress((void**)&wl, g_wl);

    const long OUT_ELEMS  = (long)Bz * Sdim * Edim;                 // 1,048,576
    const long ATTN_ELEMS = (long)Bz * Hn * Sdim * WIN;             // 4,227,072
    float* attn_out = nullptr;
    if ((long)out_size >= OUT_ELEMS + ATTN_ELEMS) attn_out = out + OUT_ELEMS;

    static bool attr_set = false;
    if (!attr_set) {
        cudaFuncSetAttribute(attn_fused_kernel,
                             cudaFuncAttributeMaxDynamicSharedMemorySize,
                             ASMW * 4);
        attr_set = true;
    }

    add_pe_pack_kernel<<<MTOK * KW / 256, 256>>>(x, xh, xl);
    pack_w_kernel<<<4 * WPK / 256, 256>>>(Wq, Wk, Wv, Wo, wh, wl);

    // Fused Q/K/V projections -> pre-split bf16 hi/lo outputs
    gemm_tc_kernel<<<dim3(MTOK / GBM, 12), 128>>>(
        xh, xl, wh, wl, bq, bk, bv,
        qh, ql, kh, kl, vh, vl, nullptr, 0);

    attn_fused_kernel<<<dim3(Sdim / QT, Hn, Bz), 128, ASMW * 4>>>(
        qh, ql, kh, kl, vh, vl, ch, cl, attn_out);

    // Output projection: fp32 out (weights index 3)
    gemm_tc_kernel<<<dim3(MTOK / GBM, 4), 128>>>(
        ch, cl, wh + 3 * WPK, wl + 3 * WPK, bo, bo, bo,
        nullptr, nullptr, nullptr, nullptr, nullptr, nullptr, out, 1);
}